// round 7
// baseline (speedup 1.0000x reference)
#include <cuda_runtime.h>
#include <cuda_bf16.h>
#include <math.h>
#include <float.h>

// ---------------------------------------------------------------------------
// Problem constants
// ---------------------------------------------------------------------------
#define BATCH 16
#define CIN   512
#define OC    512
#define HWPIX 4096                 // 64*64
#define NPIX  (BATCH*HWPIX)        // 65536
#define NA    9
#define NANCH (HWPIX*NA)           // 36864 per image
#define PRE_NMS 6000
#define POST_NMS 300
#define NEGF (-1e30f)

// Output layout: reg [B,36864,4] | cls [B,36864,2] | rois [B,300,5]
#define CLS_OFF  (BATCH*NANCH*4)
#define ROIS_OFF (CLS_OFF + BATCH*NANCH*2)

// ---------------------------------------------------------------------------
// Device scratch
// ---------------------------------------------------------------------------
__device__ float g_wt[9*CIN*OC];            // [tap][ic][oc]
__device__ float g_wk[CIN*54];              // [ic][o] o<18 cls, else reg
__device__ float g_shared[(size_t)NPIX*OC]; // NHWC shared features
__device__ float g_boxes[BATCH*NANCH*4];
__device__ float g_scores[BATCH*NANCH];
__device__ float  g_cand_s[BATCH*PRE_NMS];
__device__ float4 g_cand_b[BATCH*PRE_NMS];
__device__ float g_abase[NA*4];

// ---------------------------------------------------------------------------
// packed f32x2 helpers (each lane = independent IEEE-RN fp32 op)
// ---------------------------------------------------------------------------
__device__ __forceinline__ unsigned long long pk2(float lo, float hi) {
    unsigned long long r;
    asm("mov.b64 %0, {%1,%2};" : "=l"(r) : "f"(lo), "f"(hi));
    return r;
}
__device__ __forceinline__ unsigned long long ffma2(unsigned long long a,
                                                    unsigned long long b,
                                                    unsigned long long c) {
    unsigned long long d;
    asm("fma.rn.f32x2 %0, %1, %2, %3;" : "=l"(d) : "l"(a), "l"(b), "l"(c));
    return d;
}
__device__ __forceinline__ unsigned long long fadd2(unsigned long long a,
                                                    unsigned long long b) {
    unsigned long long d;
    asm("add.rn.f32x2 %0, %1, %2;" : "=l"(d) : "l"(a), "l"(b));
    return d;
}
__device__ __forceinline__ void upk2(unsigned long long v, float& lo, float& hi) {
    asm("mov.b64 {%0,%1}, %2;" : "=f"(lo), "=f"(hi) : "l"(v));
}

// ---------------------------------------------------------------------------
// k0a: W_share [oc][ic][3][3] -> g_wt [tap][ic][oc]
// ---------------------------------------------------------------------------
__global__ void k_wt_transform(const float* __restrict__ Wsh) {
    int idx = blockIdx.x * blockDim.x + threadIdx.x;
    if (idx >= OC * CIN * 9) return;
    int oc = idx / (CIN * 9);
    int rem = idx - oc * (CIN * 9);
    int ic = rem / 9;
    int t  = rem - ic * 9;
    g_wt[((size_t)t * CIN + ic) * OC + oc] = Wsh[idx];
}

// ---------------------------------------------------------------------------
// k0b: head weights [ic][54] and anchor base (double math, cast f32)
// ---------------------------------------------------------------------------
__global__ void k_wk_build(const float* __restrict__ Wcls, const float* __restrict__ Wreg) {
    int idx = blockIdx.x * blockDim.x + threadIdx.x;
    if (idx < CIN * 54) {
        int ic = idx / 54;
        int o  = idx - ic * 54;
        g_wk[idx] = (o < 18) ? Wcls[o * CIN + ic] : Wreg[(o - 18) * CIN + ic];
    }
    if (blockIdx.x == 0 && threadIdx.x < NA) {
        int a = threadIdx.x;
        const double ratios[3] = {0.5, 1.0, 2.0};
        const double scales[3] = {8.0, 16.0, 32.0};
        int r = a / 3, s = a % 3;
        double hh = (16.0 * scales[s]) * sqrt(ratios[r]);
        double ww = (16.0 * scales[s]) * sqrt(1.0 / ratios[r]);
        g_abase[a*4+0] = (float)(8.0 - ww/2.0);
        g_abase[a*4+1] = (float)(8.0 - hh/2.0);
        g_abase[a*4+2] = (float)(8.0 + ww/2.0);
        g_abase[a*4+3] = (float)(8.0 + hh/2.0);
    }
}

// ---------------------------------------------------------------------------
// k1: 3x3 conv + bias + relu — packed FFMA2 version.
//     BIT-EXACT accumulation preserved from the passing R6 kernel:
//       out = ((p0 + p1) + ... + p8), tap t=ky*3+kx ascending,
//       p_t = serial FMA chain over ic=0..511 ascending.
//     Outputs are PAIRED over adjacent oc into f32x2 lanes; each lane's chain
//     is bit-identical to the scalar version. A-tile stored duplicated (v,v)
//     so both FFMA2 operands load straight from smem (no repack MOVs).
// ---------------------------------------------------------------------------
#define BKK 16
__global__ __launch_bounds__(256, 1) void k_conv3x3(const float* __restrict__ x,
                                                    const float* __restrict__ bsh) {
    const int nb = blockIdx.x;          // 0..3 (oc block of 128)
    const int mb = blockIdx.y;          // 0..511
    const int b  = mb >> 5;
    const int h0 = (mb & 31) * 2;
    const int tid = threadIdx.x;
    const int tx = tid & 15, ty = tid >> 4;

    __shared__ unsigned long long As2[BKK][128+4];   // duplicated (v,v)
    __shared__ float Bs[BKK][128+4];

    unsigned long long tot2[8][4];
    unsigned long long pt2[8][4];
    #pragma unroll
    for (int r = 0; r < 8; ++r)
        #pragma unroll
        for (int cc = 0; cc < 4; ++cc) tot2[r][cc] = 0ull;

    const float* xb = x + (size_t)b * CIN * HWPIX;

    for (int t = 0; t < 9; ++t) {
        const int ky = t / 3 - 1;
        const int kx = t % 3 - 1;
        const float* wt = g_wt + (size_t)t * CIN * OC;

        #pragma unroll
        for (int r = 0; r < 8; ++r)
            #pragma unroll
            for (int cc = 0; cc < 4; ++cc) pt2[r][cc] = 0ull;

        for (int ic0 = 0; ic0 < CIN; ic0 += BKK) {
            // A tile (duplicated): As2[kk][p] = (v,v)
            #pragma unroll
            for (int i = 0; i < 8; ++i) {
                int e = i * 256 + tid;
                int kk = e >> 7, p = e & 127;
                int h = h0 + (p >> 6) + ky;
                int w = (p & 63) + kx;
                float v = 0.f;
                if ((unsigned)h < 64u && (unsigned)w < 64u)
                    v = xb[((size_t)(ic0 + kk)) * HWPIX + h * 64 + w];
                As2[kk][p] = pk2(v, v);
            }
            // B tile: Bs[kk][oc] = g_wt[t][ic0+kk][nb*128+oc]
            #pragma unroll
            for (int i = 0; i < 8; ++i) {
                int e = i * 256 + tid;
                int kk = e >> 7, oc = e & 127;
                Bs[kk][oc] = wt[(size_t)(ic0 + kk) * OC + nb * 128 + oc];
            }
            __syncthreads();
            #pragma unroll
            for (int kk = 0; kk < BKK; ++kk) {
                // a: 8 duplicated pairs (4x 16B loads)
                unsigned long long a2[8];
                {
                    const ulonglong2* ap =
                        reinterpret_cast<const ulonglong2*>(&As2[kk][ty * 8]);
                    #pragma unroll
                    for (int i = 0; i < 4; ++i) {
                        ulonglong2 v = ap[i];
                        a2[2 * i] = v.x; a2[2 * i + 1] = v.y;
                    }
                }
                // b: 4 oc-pairs (2x 16B loads)
                unsigned long long b2[4];
                {
                    const ulonglong2* bp =
                        reinterpret_cast<const ulonglong2*>(&Bs[kk][tx * 8]);
                    ulonglong2 v0 = bp[0], v1 = bp[1];
                    b2[0] = v0.x; b2[1] = v0.y; b2[2] = v1.x; b2[3] = v1.y;
                }
                #pragma unroll
                for (int r = 0; r < 8; ++r)
                    #pragma unroll
                    for (int cc = 0; cc < 4; ++cc)
                        pt2[r][cc] = ffma2(a2[r], b2[cc], pt2[r][cc]);
            }
            __syncthreads();
        }

        // sequential tap combine: tot += p_t (per-lane __fadd_rn)
        #pragma unroll
        for (int r = 0; r < 8; ++r)
            #pragma unroll
            for (int cc = 0; cc < 4; ++cc)
                tot2[r][cc] = fadd2(tot2[r][cc], pt2[r][cc]);
    }

    // epilogue: bias + relu -> NHWC
    #pragma unroll
    for (int r = 0; r < 8; ++r) {
        int p = ty * 8 + r;
        size_t rowbase = ((size_t)b * HWPIX + h0 * 64 + p) * OC + nb * 128 + tx * 8;
        #pragma unroll
        for (int cc = 0; cc < 4; ++cc) {
            float f0, f1;
            upk2(tot2[r][cc], f0, f1);
            float v0 = __fadd_rn(f0, bsh[nb * 128 + tx * 8 + 2 * cc]);
            float v1 = __fadd_rn(f1, bsh[nb * 128 + tx * 8 + 2 * cc + 1]);
            g_shared[rowbase + 2 * cc]     = fmaxf(v0, 0.f);
            g_shared[rowbase + 2 * cc + 1] = fmaxf(v1, 0.f);
        }
    }
}

// ---------------------------------------------------------------------------
// k2: 1x1 heads (serial ascending over ic) + softmax + decode/clip/min-size.
// ---------------------------------------------------------------------------
__global__ __launch_bounds__(256) void k_heads(const float* __restrict__ bcls,
                                               const float* __restrict__ breg,
                                               float* __restrict__ out) {
    __shared__ float xs[256][33];
    __shared__ float ws[32][54];
    const int tid = threadIdx.x;
    const int pixBase = blockIdx.x * 256;
    const int pix = pixBase + tid;
    const int warp = tid >> 5, lane = tid & 31;

    float acc[54];
    #pragma unroll
    for (int o = 0; o < 54; ++o) acc[o] = 0.f;

    for (int ic0 = 0; ic0 < CIN; ic0 += 32) {
        #pragma unroll 4
        for (int i = 0; i < 32; ++i) {
            int px = warp * 32 + i;
            xs[px][lane] = g_shared[(size_t)(pixBase + px) * OC + ic0 + lane];
        }
        for (int j = tid; j < 32 * 54; j += 256)
            ws[j / 54][j % 54] = g_wk[(ic0 + j / 54) * 54 + j % 54];
        __syncthreads();
        #pragma unroll
        for (int ic = 0; ic < 32; ++ic) {
            float v = xs[tid][ic];
            #pragma unroll
            for (int o = 0; o < 54; ++o)
                acc[o] = fmaf(v, ws[ic][o], acc[o]);
        }
        __syncthreads();
    }

    const int b  = pix >> 12;
    const int pi = pix & 4095;
    const int h  = pi >> 6, w = pi & 63;

    #pragma unroll
    for (int o = 0; o < 18; ++o) acc[o] = __fadd_rn(acc[o], bcls[o]);
    #pragma unroll
    for (int o = 18; o < 54; ++o) acc[o] = __fadd_rn(acc[o], breg[o - 18]);

    const float shx = (float)(w * 16);
    const float shy = (float)(h * 16);

    #pragma unroll
    for (int a = 0; a < NA; ++a) {
        float l0 = acc[2 * a], l1 = acc[2 * a + 1];
        float m = fmaxf(l0, l1);
        float e0 = expf(__fsub_rn(l0, m)), e1 = expf(__fsub_rn(l1, m));
        float s = __fadd_rn(e0, e1);
        float p0 = __fdiv_rn(e0, s), p1 = __fdiv_rn(e1, s);

        size_t n = (size_t)b * NANCH + (size_t)pi * NA + a;
        out[CLS_OFF + n * 2]     = p0;
        out[CLS_OFF + n * 2 + 1] = p1;

        float dxv = acc[18 + a * 4 + 0];
        float dyv = acc[18 + a * 4 + 1];
        float dwv = acc[18 + a * 4 + 2];
        float dhv = acc[18 + a * 4 + 3];
        out[n * 4 + 0] = dxv;
        out[n * 4 + 1] = dyv;
        out[n * 4 + 2] = dwv;
        out[n * 4 + 3] = dhv;

        float ax1 = __fadd_rn(shx, g_abase[a * 4 + 0]);
        float ay1 = __fadd_rn(shy, g_abase[a * 4 + 1]);
        float ax2 = __fadd_rn(shx, g_abase[a * 4 + 2]);
        float ay2 = __fadd_rn(shy, g_abase[a * 4 + 3]);
        float aw = __fsub_rn(ax2, ax1);
        float ah = __fsub_rn(ay2, ay1);
        float actx = __fadd_rn(ax1, __fmul_rn(0.5f, aw));
        float acty = __fadd_rn(ay1, __fmul_rn(0.5f, ah));
        float cx = __fadd_rn(__fmul_rn(dxv, aw), actx);
        float cy = __fadd_rn(__fmul_rn(dyv, ah), acty);
        float bw = __fmul_rn(expf(dwv), aw);
        float bh = __fmul_rn(expf(dhv), ah);
        float x1 = __fsub_rn(cx, __fmul_rn(0.5f, bw));
        float y1 = __fsub_rn(cy, __fmul_rn(0.5f, bh));
        float x2 = __fadd_rn(cx, __fmul_rn(0.5f, bw));
        float y2 = __fadd_rn(cy, __fmul_rn(0.5f, bh));
        x1 = fminf(fmaxf(x1, 0.f), 1024.f);
        y1 = fminf(fmaxf(y1, 0.f), 1024.f);
        x2 = fminf(fmaxf(x2, 0.f), 1024.f);
        y2 = fminf(fmaxf(y2, 0.f), 1024.f);
        float wsz = __fsub_rn(x2, x1), hsz = __fsub_rn(y2, y1);
        float sc = (wsz >= 16.f && hsz >= 16.f) ? p1 : NEGF;

        g_boxes[n * 4 + 0] = x1;
        g_boxes[n * 4 + 1] = y1;
        g_boxes[n * 4 + 2] = x2;
        g_boxes[n * 4 + 3] = y2;
        g_scores[n] = sc;
    }
}

// ---------------------------------------------------------------------------
// k3: per-image exact top-6000 set, stable (index-ordered) compaction
// ---------------------------------------------------------------------------
__device__ __forceinline__ unsigned score_key(float f) {
    unsigned u = __float_as_uint(f);
    return (u & 0x80000000u) ? ~u : (u | 0x80000000u);
}

__global__ __launch_bounds__(1024) void k_select() {
    const int b = blockIdx.x;
    const int tid = threadIdx.x;
    const int warp = tid >> 5, lane = tid & 31;
    const float* sc = g_scores + (size_t)b * NANCH;
    __shared__ unsigned hist[256];
    __shared__ unsigned sel_prefix;
    __shared__ int sel_needed;
    __shared__ int warpG[32], warpE[32];
    __shared__ int base_g, base_e;

    unsigned prefix = 0, maskHi = 0;
    int needed = PRE_NMS;

    for (int shift = 24; shift >= 0; shift -= 8) {
        for (int i = tid; i < 256; i += 1024) hist[i] = 0;
        __syncthreads();
        for (int j = tid; j < NANCH; j += 1024) {
            unsigned u = score_key(sc[j]);
            if ((u & maskHi) == prefix)
                atomicAdd(&hist[(u >> shift) & 255u], 1u);
        }
        __syncthreads();
        if (tid == 0) {
            int need = needed;
            int bsel = 0;
            for (int bin = 255; bin >= 0; --bin) {
                int c = (int)hist[bin];
                if (c >= need) { bsel = bin; break; }
                need -= c;
            }
            sel_needed = need;
            sel_prefix = prefix | ((unsigned)bsel << shift);
        }
        __syncthreads();
        needed = sel_needed;
        prefix = sel_prefix;
        maskHi |= (0xFFu << shift);
        __syncthreads();
    }

    const unsigned T = prefix;
    const int needEq = needed;
    const int cgt = PRE_NMS - needEq;

    if (tid == 0) { base_g = 0; base_e = 0; }
    __syncthreads();

    const unsigned lt_mask = (1u << lane) - 1u;
    const float4* bp = reinterpret_cast<const float4*>(g_boxes);

    for (int chunk = 0; chunk < NANCH; chunk += 1024) {
        int j = chunk + tid;
        float s = sc[j];
        unsigned u = score_key(s);
        bool isG = (u > T);
        bool isE = (u == T);
        unsigned gm = __ballot_sync(0xffffffffu, isG);
        unsigned em = __ballot_sync(0xffffffffu, isE);
        if (lane == 0) { warpG[warp] = __popc(gm); warpE[warp] = __popc(em); }
        __syncthreads();
        if (warp == 0) {
            int g = warpG[lane], e = warpE[lane];
            #pragma unroll
            for (int off = 1; off < 32; off <<= 1) {
                int go = __shfl_up_sync(0xffffffffu, g, off);
                int eo = __shfl_up_sync(0xffffffffu, e, off);
                if (lane >= off) { g += go; e += eo; }
            }
            warpG[lane] = g; warpE[lane] = e;
        }
        __syncthreads();
        int wbaseG = (warp == 0) ? 0 : warpG[warp - 1];
        int wbaseE = (warp == 0) ? 0 : warpE[warp - 1];
        int slot = -1;
        if (isG) {
            slot = base_g + wbaseG + __popc(gm & lt_mask);
        } else if (isE) {
            int er = base_e + wbaseE + __popc(em & lt_mask);
            if (er < needEq) slot = cgt + er;
        }
        if (slot >= 0) {
            size_t n = (size_t)b * NANCH + j;
            g_cand_s[b * PRE_NMS + slot] = s;
            g_cand_b[b * PRE_NMS + slot] = bp[n];
        }
        __syncthreads();
        if (tid == 0) { base_g += warpG[31]; base_e += warpE[31]; }
        __syncthreads();
    }
}

// ---------------------------------------------------------------------------
// k4: greedy NMS (argmax ties -> smallest slot == smallest anchor index)
// ---------------------------------------------------------------------------
#define NMS_THREADS 512
__global__ void k_nms(float* __restrict__ out) {
    extern __shared__ float smem[];
    float*  sc = smem;                                    // [6016]
    float4* bx = reinterpret_cast<float4*>(smem + 6016);  // [6000]
    float*  wv = smem + 6016 + PRE_NMS * 4;               // [16]
    int*    wi = reinterpret_cast<int*>(wv + 16);         // [16]
    float*  bestv = reinterpret_cast<float*>(wi + 16);
    int*    besti = reinterpret_cast<int*>(bestv + 1);

    const int b = blockIdx.x;
    const int tid = threadIdx.x;
    const int warp = tid >> 5, lane = tid & 31;

    for (int j = tid; j < PRE_NMS; j += NMS_THREADS) {
        sc[j] = g_cand_s[b * PRE_NMS + j];
        bx[j] = g_cand_b[b * PRE_NMS + j];
    }
    __syncthreads();

    for (int i = 0; i < POST_NMS; ++i) {
        float vm = -INFINITY; int im = 0x7fffffff;
        for (int j = tid; j < PRE_NMS; j += NMS_THREADS) {
            float v = sc[j];
            if (v > vm) { vm = v; im = j; }
        }
        #pragma unroll
        for (int off = 16; off > 0; off >>= 1) {
            float ov = __shfl_down_sync(0xffffffffu, vm, off);
            int   oi = __shfl_down_sync(0xffffffffu, im, off);
            if (ov > vm || (ov == vm && oi < im)) { vm = ov; im = oi; }
        }
        if (lane == 0) { wv[warp] = vm; wi[warp] = im; }
        __syncthreads();
        if (warp == 0) {
            float v = (lane < NMS_THREADS / 32) ? wv[lane] : -INFINITY;
            int   x = (lane < NMS_THREADS / 32) ? wi[lane] : 0x7fffffff;
            #pragma unroll
            for (int off = 8; off > 0; off >>= 1) {
                float ov = __shfl_down_sync(0xffffffffu, v, off);
                int   oi = __shfl_down_sync(0xffffffffu, x, off);
                if (ov > v || (ov == v && oi < x)) { v = ov; x = oi; }
            }
            if (lane == 0) { *bestv = v; *besti = x; }
        }
        __syncthreads();

        float m = *bestv;
        int mi = *besti;
        bool valid = m > NEGF;

        if (!valid) {
            int remain = (POST_NMS - i) * 5;
            float* ro = out + ROIS_OFF + ((size_t)b * POST_NMS + i) * 5;
            for (int k = tid; k < remain; k += NMS_THREADS) ro[k] = 0.f;
            return;
        }

        float4 B = bx[mi];
        if (tid == 0) {
            float* ro = out + ROIS_OFF + ((size_t)b * POST_NMS + i) * 5;
            ro[0] = m; ro[1] = B.x; ro[2] = B.y; ro[3] = B.z; ro[4] = B.w;
        }
        float a1 = __fmul_rn(__fsub_rn(B.z, B.x), __fsub_rn(B.w, B.y));
        for (int j = tid; j < PRE_NMS; j += NMS_THREADS) {
            float v = sc[j];
            if (v == NEGF) continue;
            float4 c = bx[j];
            float x1 = fmaxf(B.x, c.x);
            float y1 = fmaxf(B.y, c.y);
            float x2 = fminf(B.z, c.z);
            float y2 = fminf(B.w, c.w);
            float inter = __fmul_rn(fmaxf(__fsub_rn(x2, x1), 0.f),
                                    fmaxf(__fsub_rn(y2, y1), 0.f));
            float a2 = __fmul_rn(__fsub_rn(c.z, c.x), __fsub_rn(c.w, c.y));
            float denom = __fadd_rn(__fsub_rn(__fadd_rn(a1, a2), inter), 1e-9f);
            float iou = __fdiv_rn(inter, denom);
            if (iou >= 0.7f) sc[j] = NEGF;
        }
        __syncthreads();
    }
}

// ---------------------------------------------------------------------------
// launch
// ---------------------------------------------------------------------------
extern "C" void kernel_launch(void* const* d_in, const int* in_sizes, int n_in,
                              void* d_out, int out_size) {
    (void)in_sizes; (void)n_in; (void)out_size;
    const float* x     = (const float*)d_in[0];
    const float* Wsh   = (const float*)d_in[1];
    const float* bsh   = (const float*)d_in[2];
    const float* Wcls  = (const float*)d_in[3];
    const float* bcls  = (const float*)d_in[4];
    const float* Wreg  = (const float*)d_in[5];
    const float* breg  = (const float*)d_in[6];
    float* out = (float*)d_out;

    k_wt_transform<<<(OC*CIN*9 + 255) / 256, 256>>>(Wsh);
    k_wk_build<<<(CIN*54 + 255) / 256, 256>>>(Wcls, Wreg);

    dim3 cgrid(4, 512);
    k_conv3x3<<<cgrid, 256>>>(x, bsh);

    k_heads<<<NPIX / 256, 256>>>(bcls, breg, out);

    k_select<<<BATCH, 1024>>>();

    int smem_bytes = (6016 + PRE_NMS * 4) * 4 + 16 * 4 + 16 * 4 + 8;
    cudaFuncSetAttribute(k_nms, cudaFuncAttributeMaxDynamicSharedMemorySize, smem_bytes);
    k_nms<<<BATCH, NMS_THREADS, smem_bytes>>>(out);
}

// round 8
// speedup vs baseline: 1.0946x; 1.0946x over previous
#include <cuda_runtime.h>
#include <cuda_bf16.h>
#include <math.h>
#include <float.h>

// ---------------------------------------------------------------------------
// Problem constants
// ---------------------------------------------------------------------------
#define BATCH 16
#define CIN   512
#define OC    512
#define HWPIX 4096                 // 64*64
#define NPIX  (BATCH*HWPIX)        // 65536
#define NA    9
#define NANCH (HWPIX*NA)           // 36864 per image
#define PRE_NMS 6000
#define POST_NMS 300
#define NEGF (-1e30f)

// Output layout: reg [B,36864,4] | cls [B,36864,2] | rois [B,300,5]
#define CLS_OFF  (BATCH*NANCH*4)
#define ROIS_OFF (CLS_OFF + BATCH*NANCH*2)

// ---------------------------------------------------------------------------
// Device scratch
// ---------------------------------------------------------------------------
__device__ float g_wt[9*CIN*OC];            // [tap][ic][oc]
__device__ float g_wk[CIN*54];              // [ic][o] o<18 cls, else reg
__device__ float g_shared[(size_t)NPIX*OC]; // NHWC shared features
__device__ float g_boxes[BATCH*NANCH*4];
__device__ float g_scores[BATCH*NANCH];
__device__ float  g_cand_s[BATCH*PRE_NMS];
__device__ float4 g_cand_b[BATCH*PRE_NMS];
__device__ float g_abase[NA*4];

// ---------------------------------------------------------------------------
// k0a: W_share [oc][ic][3][3] -> g_wt [tap][ic][oc]
// ---------------------------------------------------------------------------
__global__ void k_wt_transform(const float* __restrict__ Wsh) {
    int idx = blockIdx.x * blockDim.x + threadIdx.x;
    if (idx >= OC * CIN * 9) return;
    int oc = idx / (CIN * 9);
    int rem = idx - oc * (CIN * 9);
    int ic = rem / 9;
    int t  = rem - ic * 9;
    g_wt[((size_t)t * CIN + ic) * OC + oc] = Wsh[idx];
}

// ---------------------------------------------------------------------------
// k0b: head weights [ic][54] and anchor base (double math, cast f32)
// ---------------------------------------------------------------------------
__global__ void k_wk_build(const float* __restrict__ Wcls, const float* __restrict__ Wreg) {
    int idx = blockIdx.x * blockDim.x + threadIdx.x;
    if (idx < CIN * 54) {
        int ic = idx / 54;
        int o  = idx - ic * 54;
        g_wk[idx] = (o < 18) ? Wcls[o * CIN + ic] : Wreg[(o - 18) * CIN + ic];
    }
    if (blockIdx.x == 0 && threadIdx.x < NA) {
        int a = threadIdx.x;
        const double ratios[3] = {0.5, 1.0, 2.0};
        const double scales[3] = {8.0, 16.0, 32.0};
        int r = a / 3, s = a % 3;
        double hh = (16.0 * scales[s]) * sqrt(ratios[r]);
        double ww = (16.0 * scales[s]) * sqrt(1.0 / ratios[r]);
        g_abase[a*4+0] = (float)(8.0 - ww/2.0);
        g_abase[a*4+1] = (float)(8.0 - hh/2.0);
        g_abase[a*4+2] = (float)(8.0 + ww/2.0);
        g_abase[a*4+3] = (float)(8.0 + hh/2.0);
    }
}

// ---------------------------------------------------------------------------
// k1: 3x3 conv + bias + relu — EXACT R6 kernel (passing, bit-pattern frozen):
//     out = ((p0 + p1) + ... + p8), tap t=ky*3+kx ascending,
//     p_t = serial scalar FMA chain over ic=0..511 ascending.
//     DO NOT modify the accumulation structure.
// ---------------------------------------------------------------------------
#define BKK 16
__global__ __launch_bounds__(256, 1) void k_conv3x3(const float* __restrict__ x,
                                                    const float* __restrict__ bsh) {
    const int nb = blockIdx.x;          // 0..3 (oc block of 128)
    const int mb = blockIdx.y;          // 0..511
    const int b  = mb >> 5;
    const int h0 = (mb & 31) * 2;
    const int tid = threadIdx.x;
    const int tx = tid & 15, ty = tid >> 4;

    __shared__ float As[BKK][128+4];
    __shared__ float Bs[BKK][128+4];

    float tot[8][8];
    float pt[8][8];
    #pragma unroll
    for (int r = 0; r < 8; ++r)
        #pragma unroll
        for (int c = 0; c < 8; ++c) tot[r][c] = 0.f;

    const float* xb = x + (size_t)b * CIN * HWPIX;

    for (int t = 0; t < 9; ++t) {
        const int ky = t / 3 - 1;
        const int kx = t % 3 - 1;
        const float* wt = g_wt + (size_t)t * CIN * OC;

        #pragma unroll
        for (int r = 0; r < 8; ++r)
            #pragma unroll
            for (int c = 0; c < 8; ++c) pt[r][c] = 0.f;

        for (int ic0 = 0; ic0 < CIN; ic0 += BKK) {
            #pragma unroll
            for (int i = 0; i < 8; ++i) {
                int e = i * 256 + tid;
                int kk = e >> 7, p = e & 127;
                int h = h0 + (p >> 6) + ky;
                int w = (p & 63) + kx;
                float v = 0.f;
                if ((unsigned)h < 64u && (unsigned)w < 64u)
                    v = xb[((size_t)(ic0 + kk)) * HWPIX + h * 64 + w];
                As[kk][p] = v;
            }
            #pragma unroll
            for (int i = 0; i < 8; ++i) {
                int e = i * 256 + tid;
                int kk = e >> 7, oc = e & 127;
                Bs[kk][oc] = wt[(size_t)(ic0 + kk) * OC + nb * 128 + oc];
            }
            __syncthreads();
            #pragma unroll
            for (int kk = 0; kk < BKK; ++kk) {
                float a[8], bb[8];
                #pragma unroll
                for (int r = 0; r < 8; ++r) a[r] = As[kk][ty * 8 + r];
                #pragma unroll
                for (int c = 0; c < 8; ++c) bb[c] = Bs[kk][tx * 8 + c];
                #pragma unroll
                for (int r = 0; r < 8; ++r)
                    #pragma unroll
                    for (int c = 0; c < 8; ++c)
                        pt[r][c] = fmaf(a[r], bb[c], pt[r][c]);
            }
            __syncthreads();
        }

        #pragma unroll
        for (int r = 0; r < 8; ++r)
            #pragma unroll
            for (int c = 0; c < 8; ++c)
                tot[r][c] = __fadd_rn(tot[r][c], pt[r][c]);
    }

    #pragma unroll
    for (int r = 0; r < 8; ++r) {
        int p = ty * 8 + r;
        size_t rowbase = ((size_t)b * HWPIX + h0 * 64 + p) * OC + nb * 128 + tx * 8;
        #pragma unroll
        for (int c = 0; c < 8; ++c) {
            float v = __fadd_rn(tot[r][c], bsh[nb * 128 + tx * 8 + c]);
            g_shared[rowbase + c] = fmaxf(v, 0.f);
        }
    }
}

// ---------------------------------------------------------------------------
// k2: 1x1 heads + softmax + decode. Weights vectorized to float4 (LDS.128
//     broadcast) to cut LDS issue count; per-output serial ic chain unchanged
//     (acc2[o] for o<54 gets identical weights in identical order).
// ---------------------------------------------------------------------------
__global__ __launch_bounds__(256) void k_heads(const float* __restrict__ bcls,
                                               const float* __restrict__ breg,
                                               float* __restrict__ out) {
    __shared__ float xs[256][33];
    __shared__ float4 ws4[32][14];      // 56 padded outputs per ic
    const int tid = threadIdx.x;
    const int pixBase = blockIdx.x * 256;
    const int pix = pixBase + tid;
    const int warp = tid >> 5, lane = tid & 31;

    float acc2[56];
    #pragma unroll
    for (int o = 0; o < 56; ++o) acc2[o] = 0.f;

    for (int ic0 = 0; ic0 < CIN; ic0 += 32) {
        #pragma unroll 4
        for (int i = 0; i < 32; ++i) {
            int px = warp * 32 + i;
            xs[px][lane] = g_shared[(size_t)(pixBase + px) * OC + ic0 + lane];
        }
        for (int j = tid; j < 32 * 56; j += 256) {
            int ic = j / 56, o = j - ic * 56;
            float v = (o < 54) ? g_wk[(ic0 + ic) * 54 + o] : 0.f;
            reinterpret_cast<float*>(&ws4[ic][0])[o] = v;
        }
        __syncthreads();
        #pragma unroll
        for (int ic = 0; ic < 32; ++ic) {
            float v = xs[tid][ic];
            #pragma unroll
            for (int o4 = 0; o4 < 14; ++o4) {
                float4 w = ws4[ic][o4];
                acc2[o4 * 4 + 0] = fmaf(v, w.x, acc2[o4 * 4 + 0]);
                acc2[o4 * 4 + 1] = fmaf(v, w.y, acc2[o4 * 4 + 1]);
                acc2[o4 * 4 + 2] = fmaf(v, w.z, acc2[o4 * 4 + 2]);
                acc2[o4 * 4 + 3] = fmaf(v, w.w, acc2[o4 * 4 + 3]);
            }
        }
        __syncthreads();
    }

    float* acc = acc2;   // first 54 are the real outputs

    const int b  = pix >> 12;
    const int pi = pix & 4095;
    const int h  = pi >> 6, w = pi & 63;

    #pragma unroll
    for (int o = 0; o < 18; ++o) acc[o] = __fadd_rn(acc[o], bcls[o]);
    #pragma unroll
    for (int o = 18; o < 54; ++o) acc[o] = __fadd_rn(acc[o], breg[o - 18]);

    const float shx = (float)(w * 16);
    const float shy = (float)(h * 16);

    #pragma unroll
    for (int a = 0; a < NA; ++a) {
        float l0 = acc[2 * a], l1 = acc[2 * a + 1];
        float m = fmaxf(l0, l1);
        float e0 = expf(__fsub_rn(l0, m)), e1 = expf(__fsub_rn(l1, m));
        float s = __fadd_rn(e0, e1);
        float p0 = __fdiv_rn(e0, s), p1 = __fdiv_rn(e1, s);

        size_t n = (size_t)b * NANCH + (size_t)pi * NA + a;
        out[CLS_OFF + n * 2]     = p0;
        out[CLS_OFF + n * 2 + 1] = p1;

        float dxv = acc[18 + a * 4 + 0];
        float dyv = acc[18 + a * 4 + 1];
        float dwv = acc[18 + a * 4 + 2];
        float dhv = acc[18 + a * 4 + 3];
        out[n * 4 + 0] = dxv;
        out[n * 4 + 1] = dyv;
        out[n * 4 + 2] = dwv;
        out[n * 4 + 3] = dhv;

        float ax1 = __fadd_rn(shx, g_abase[a * 4 + 0]);
        float ay1 = __fadd_rn(shy, g_abase[a * 4 + 1]);
        float ax2 = __fadd_rn(shx, g_abase[a * 4 + 2]);
        float ay2 = __fadd_rn(shy, g_abase[a * 4 + 3]);
        float aw = __fsub_rn(ax2, ax1);
        float ah = __fsub_rn(ay2, ay1);
        float actx = __fadd_rn(ax1, __fmul_rn(0.5f, aw));
        float acty = __fadd_rn(ay1, __fmul_rn(0.5f, ah));
        float cx = __fadd_rn(__fmul_rn(dxv, aw), actx);
        float cy = __fadd_rn(__fmul_rn(dyv, ah), acty);
        float bw = __fmul_rn(expf(dwv), aw);
        float bh = __fmul_rn(expf(dhv), ah);
        float x1 = __fsub_rn(cx, __fmul_rn(0.5f, bw));
        float y1 = __fsub_rn(cy, __fmul_rn(0.5f, bh));
        float x2 = __fadd_rn(cx, __fmul_rn(0.5f, bw));
        float y2 = __fadd_rn(cy, __fmul_rn(0.5f, bh));
        x1 = fminf(fmaxf(x1, 0.f), 1024.f);
        y1 = fminf(fmaxf(y1, 0.f), 1024.f);
        x2 = fminf(fmaxf(x2, 0.f), 1024.f);
        y2 = fminf(fmaxf(y2, 0.f), 1024.f);
        float wsz = __fsub_rn(x2, x1), hsz = __fsub_rn(y2, y1);
        float sc = (wsz >= 16.f && hsz >= 16.f) ? p1 : NEGF;

        g_boxes[n * 4 + 0] = x1;
        g_boxes[n * 4 + 1] = y1;
        g_boxes[n * 4 + 2] = x2;
        g_boxes[n * 4 + 3] = y2;
        g_scores[n] = sc;
    }
}

// ---------------------------------------------------------------------------
// k3: per-image exact top-6000 set, stable (index-ordered) compaction
// ---------------------------------------------------------------------------
__device__ __forceinline__ unsigned score_key(float f) {
    unsigned u = __float_as_uint(f);
    return (u & 0x80000000u) ? ~u : (u | 0x80000000u);
}

__global__ __launch_bounds__(1024) void k_select() {
    const int b = blockIdx.x;
    const int tid = threadIdx.x;
    const int warp = tid >> 5, lane = tid & 31;
    const float* sc = g_scores + (size_t)b * NANCH;
    __shared__ unsigned hist[256];
    __shared__ unsigned sel_prefix;
    __shared__ int sel_needed;
    __shared__ int warpG[32], warpE[32];
    __shared__ int base_g, base_e;

    unsigned prefix = 0, maskHi = 0;
    int needed = PRE_NMS;

    for (int shift = 24; shift >= 0; shift -= 8) {
        for (int i = tid; i < 256; i += 1024) hist[i] = 0;
        __syncthreads();
        for (int j = tid; j < NANCH; j += 1024) {
            unsigned u = score_key(sc[j]);
            if ((u & maskHi) == prefix)
                atomicAdd(&hist[(u >> shift) & 255u], 1u);
        }
        __syncthreads();
        if (tid == 0) {
            int need = needed;
            int bsel = 0;
            for (int bin = 255; bin >= 0; --bin) {
                int c = (int)hist[bin];
                if (c >= need) { bsel = bin; break; }
                need -= c;
            }
            sel_needed = need;
            sel_prefix = prefix | ((unsigned)bsel << shift);
        }
        __syncthreads();
        needed = sel_needed;
        prefix = sel_prefix;
        maskHi |= (0xFFu << shift);
        __syncthreads();
    }

    const unsigned T = prefix;
    const int needEq = needed;
    const int cgt = PRE_NMS - needEq;

    if (tid == 0) { base_g = 0; base_e = 0; }
    __syncthreads();

    const unsigned lt_mask = (1u << lane) - 1u;
    const float4* bp = reinterpret_cast<const float4*>(g_boxes);

    for (int chunk = 0; chunk < NANCH; chunk += 1024) {
        int j = chunk + tid;
        float s = sc[j];
        unsigned u = score_key(s);
        bool isG = (u > T);
        bool isE = (u == T);
        unsigned gm = __ballot_sync(0xffffffffu, isG);
        unsigned em = __ballot_sync(0xffffffffu, isE);
        if (lane == 0) { warpG[warp] = __popc(gm); warpE[warp] = __popc(em); }
        __syncthreads();
        if (warp == 0) {
            int g = warpG[lane], e = warpE[lane];
            #pragma unroll
            for (int off = 1; off < 32; off <<= 1) {
                int go = __shfl_up_sync(0xffffffffu, g, off);
                int eo = __shfl_up_sync(0xffffffffu, e, off);
                if (lane >= off) { g += go; e += eo; }
            }
            warpG[lane] = g; warpE[lane] = e;
        }
        __syncthreads();
        int wbaseG = (warp == 0) ? 0 : warpG[warp - 1];
        int wbaseE = (warp == 0) ? 0 : warpE[warp - 1];
        int slot = -1;
        if (isG) {
            slot = base_g + wbaseG + __popc(gm & lt_mask);
        } else if (isE) {
            int er = base_e + wbaseE + __popc(em & lt_mask);
            if (er < needEq) slot = cgt + er;
        }
        if (slot >= 0) {
            size_t n = (size_t)b * NANCH + j;
            g_cand_s[b * PRE_NMS + slot] = s;
            g_cand_b[b * PRE_NMS + slot] = bp[n];
        }
        __syncthreads();
        if (tid == 0) { base_g += warpG[31]; base_e += warpE[31]; }
        __syncthreads();
    }
}

// ---------------------------------------------------------------------------
// k4: sort-then-sweep greedy NMS.
//     One bitonic sort (key = score desc, tie = smallest slot/anchor index)
//     reproduces lax.top_k ordering + first-occurrence argmax exactly; then
//     each accept round is just "advance to next unsuppressed" + parallel
//     suppression. IoU rounding identical to the passing kernel.
// ---------------------------------------------------------------------------
#define NMS_THREADS 512
#define NMS_N 8192                      // padded pow2 for bitonic
__global__ __launch_bounds__(NMS_THREADS) void k_nms(float* __restrict__ out) {
    extern __shared__ unsigned char smem_raw[];
    float4* bx = reinterpret_cast<float4*>(smem_raw);                     // [6000]
    unsigned long long* keys =
        reinterpret_cast<unsigned long long*>(smem_raw + PRE_NMS * 16);   // [8192]
    float* sc = reinterpret_cast<float*>(smem_raw + PRE_NMS * 16 + NMS_N * 8); // [6000]
    unsigned char* sup = smem_raw + PRE_NMS * 16 + NMS_N * 8 + PRE_NMS * 4;    // [8192]
    int* ctrl = reinterpret_cast<int*>(sup + NMS_N);                      // [4]

    const int b = blockIdx.x;
    const int tid = threadIdx.x;

    // load candidates + build sort keys.
    // key' = ~( (score_key(s) << 32) | (u32)(~slot) ); ascending sort of key'
    // == descending (score, then smallest slot first). slot = (u32)key'.
    for (int j = tid; j < NMS_N; j += NMS_THREADS) {
        if (j < PRE_NMS) {
            float s = g_cand_s[b * PRE_NMS + j];
            sc[j] = s;
            bx[j] = g_cand_b[b * PRE_NMS + j];
            unsigned long long key =
                ((unsigned long long)score_key(s) << 32) | (unsigned)(~j);
            keys[j] = ~key;
        } else {
            keys[j] = ~0ull;    // pad: sorts last
        }
        sup[j] = 0;
    }
    if (tid == 0) ctrl[0] = 0;   // current position
    __syncthreads();

    // bitonic ascending sort of keys[0..8191]
    for (int k = 2; k <= NMS_N; k <<= 1) {
        for (int j = k >> 1; j > 0; j >>= 1) {
            for (int t = tid; t < NMS_N; t += NMS_THREADS) {
                int partner = t ^ j;
                if (partner > t) {
                    bool up = ((t & k) == 0);
                    unsigned long long a = keys[t], c = keys[partner];
                    if (up ? (a > c) : (a < c)) {
                        keys[t] = c; keys[partner] = a;
                    }
                }
            }
            __syncthreads();
        }
    }

    // greedy sweep
    for (int it = 0; it < POST_NMS; ++it) {
        if (tid == 0) {
            int p = ctrl[0];
            while (p < PRE_NMS && sup[p]) ++p;
            ctrl[0] = p;
        }
        __syncthreads();
        int pos = ctrl[0];

        bool valid = false;
        int slot = 0;
        float m = 0.f;
        if (pos < PRE_NMS) {
            slot = (int)(unsigned)keys[pos];
            m = sc[slot];
            valid = (m > NEGF);
        }

        if (!valid) {
            int remain = (POST_NMS - it) * 5;
            float* ro = out + ROIS_OFF + ((size_t)b * POST_NMS + it) * 5;
            for (int k2 = tid; k2 < remain; k2 += NMS_THREADS) ro[k2] = 0.f;
            return;
        }

        float4 B = bx[slot];
        if (tid == 0) {
            float* ro = out + ROIS_OFF + ((size_t)b * POST_NMS + it) * 5;
            ro[0] = m; ro[1] = B.x; ro[2] = B.y; ro[3] = B.z; ro[4] = B.w;
            sup[pos] = 1;
        }
        float a1 = __fmul_rn(__fsub_rn(B.z, B.x), __fsub_rn(B.w, B.y));
        for (int p2 = pos + 1 + tid; p2 < PRE_NMS; p2 += NMS_THREADS) {
            if (sup[p2]) continue;
            int s2 = (int)(unsigned)keys[p2];
            float4 c = bx[s2];
            float x1 = fmaxf(B.x, c.x);
            float y1 = fmaxf(B.y, c.y);
            float x2 = fminf(B.z, c.z);
            float y2 = fminf(B.w, c.w);
            float inter = __fmul_rn(fmaxf(__fsub_rn(x2, x1), 0.f),
                                    fmaxf(__fsub_rn(y2, y1), 0.f));
            float a2 = __fmul_rn(__fsub_rn(c.z, c.x), __fsub_rn(c.w, c.y));
            float denom = __fadd_rn(__fsub_rn(__fadd_rn(a1, a2), inter), 1e-9f);
            float iou = __fdiv_rn(inter, denom);
            if (iou >= 0.7f) sup[p2] = 1;
        }
        __syncthreads();
    }
}

// ---------------------------------------------------------------------------
// launch
// ---------------------------------------------------------------------------
extern "C" void kernel_launch(void* const* d_in, const int* in_sizes, int n_in,
                              void* d_out, int out_size) {
    (void)in_sizes; (void)n_in; (void)out_size;
    const float* x     = (const float*)d_in[0];
    const float* Wsh   = (const float*)d_in[1];
    const float* bsh   = (const float*)d_in[2];
    const float* Wcls  = (const float*)d_in[3];
    const float* bcls  = (const float*)d_in[4];
    const float* Wreg  = (const float*)d_in[5];
    const float* breg  = (const float*)d_in[6];
    float* out = (float*)d_out;

    k_wt_transform<<<(OC*CIN*9 + 255) / 256, 256>>>(Wsh);
    k_wk_build<<<(CIN*54 + 255) / 256, 256>>>(Wcls, Wreg);

    dim3 cgrid(4, 512);
    k_conv3x3<<<cgrid, 256>>>(x, bsh);

    k_heads<<<NPIX / 256, 256>>>(bcls, breg, out);

    k_select<<<BATCH, 1024>>>();

    int smem_bytes = PRE_NMS * 16 + NMS_N * 8 + PRE_NMS * 4 + NMS_N + 16;
    cudaFuncSetAttribute(k_nms, cudaFuncAttributeMaxDynamicSharedMemorySize, smem_bytes);
    k_nms<<<BATCH, NMS_THREADS, smem_bytes>>>(out);
}

// round 9
// speedup vs baseline: 1.1979x; 1.0943x over previous
#include <cuda_runtime.h>
#include <cuda_bf16.h>
#include <math.h>
#include <float.h>

// ---------------------------------------------------------------------------
// Problem constants
// ---------------------------------------------------------------------------
#define BATCH 16
#define CIN   512
#define OC    512
#define HWPIX 4096                 // 64*64
#define NPIX  (BATCH*HWPIX)        // 65536
#define NA    9
#define NANCH (HWPIX*NA)           // 36864 per image
#define PRE_NMS 6000
#define POST_NMS 300
#define NEGF (-1e30f)

// Output layout: reg [B,36864,4] | cls [B,36864,2] | rois [B,300,5]
#define CLS_OFF  (BATCH*NANCH*4)
#define ROIS_OFF (CLS_OFF + BATCH*NANCH*2)

// ---------------------------------------------------------------------------
// Device scratch
// ---------------------------------------------------------------------------
__device__ float g_wt[9*CIN*OC];            // [tap][ic][oc]
__device__ float g_wk[CIN*54];              // [ic][o] o<18 cls, else reg
__device__ float g_shared[(size_t)NPIX*OC]; // NHWC shared features
__device__ float g_boxes[BATCH*NANCH*4];
__device__ float g_scores[BATCH*NANCH];
__device__ float  g_cand_s[BATCH*PRE_NMS];
__device__ float4 g_cand_b[BATCH*PRE_NMS];
__device__ float g_abase[NA*4];

// ---------------------------------------------------------------------------
// k0a: W_share [oc][ic][3][3] -> g_wt [tap][ic][oc]
// ---------------------------------------------------------------------------
__global__ void k_wt_transform(const float* __restrict__ Wsh) {
    int idx = blockIdx.x * blockDim.x + threadIdx.x;
    if (idx >= OC * CIN * 9) return;
    int oc = idx / (CIN * 9);
    int rem = idx - oc * (CIN * 9);
    int ic = rem / 9;
    int t  = rem - ic * 9;
    g_wt[((size_t)t * CIN + ic) * OC + oc] = Wsh[idx];
}

// ---------------------------------------------------------------------------
// k0b: head weights [ic][54] and anchor base (double math, cast f32)
// ---------------------------------------------------------------------------
__global__ void k_wk_build(const float* __restrict__ Wcls, const float* __restrict__ Wreg) {
    int idx = blockIdx.x * blockDim.x + threadIdx.x;
    if (idx < CIN * 54) {
        int ic = idx / 54;
        int o  = idx - ic * 54;
        g_wk[idx] = (o < 18) ? Wcls[o * CIN + ic] : Wreg[(o - 18) * CIN + ic];
    }
    if (blockIdx.x == 0 && threadIdx.x < NA) {
        int a = threadIdx.x;
        const double ratios[3] = {0.5, 1.0, 2.0};
        const double scales[3] = {8.0, 16.0, 32.0};
        int r = a / 3, s = a % 3;
        double hh = (16.0 * scales[s]) * sqrt(ratios[r]);
        double ww = (16.0 * scales[s]) * sqrt(1.0 / ratios[r]);
        g_abase[a*4+0] = (float)(8.0 - ww/2.0);
        g_abase[a*4+1] = (float)(8.0 - hh/2.0);
        g_abase[a*4+2] = (float)(8.0 + ww/2.0);
        g_abase[a*4+3] = (float)(8.0 + hh/2.0);
    }
}

// ---------------------------------------------------------------------------
// k1: 3x3 conv + bias + relu — R6 accumulation (frozen bit pattern):
//       out = ((p0 + p1) + ... + p8), tap t=ky*3+kx ascending,
//       p_t = serial scalar FMA chain over ic=0..511 ascending.
//     NEW: software-pipelined double-buffered smem (1 sync/chunk, prefetch
//     overlapped with FFMAs). Per-accumulator op order is IDENTICAL.
// ---------------------------------------------------------------------------
#define BKK 16
#define NCHUNK (9 * (CIN / BKK))      // 288
__global__ __launch_bounds__(256, 1) void k_conv3x3(const float* __restrict__ x,
                                                    const float* __restrict__ bsh) {
    const int nb = blockIdx.x;          // 0..3 (oc block of 128)
    const int mb = blockIdx.y;          // 0..511
    const int b  = mb >> 5;
    const int h0 = (mb & 31) * 2;
    const int tid = threadIdx.x;
    const int tx = tid & 15, ty = tid >> 4;

    __shared__ float As[2][BKK][132];
    __shared__ float Bs[2][BKK][132];

    float tot[8][8];
    float pt[8][8];
    #pragma unroll
    for (int r = 0; r < 8; ++r)
        #pragma unroll
        for (int c = 0; c < 8; ++c) tot[r][c] = 0.f;

    const float* xb = x + (size_t)b * CIN * HWPIX;

    float ra[8], rb[8];

    // prefetch helper (same element mapping as the R6 loads)
    auto prefetch = [&](int g) {
        int t = g >> 5;
        int ic0 = (g & 31) * BKK;
        int ky = t / 3 - 1;
        int kx = t % 3 - 1;
        const float* wt = g_wt + (size_t)t * CIN * OC;
        #pragma unroll
        for (int i = 0; i < 8; ++i) {
            int e = i * 256 + tid;
            int kk = e >> 7, p = e & 127;
            int h = h0 + (p >> 6) + ky;
            int w = (p & 63) + kx;
            float v = 0.f;
            if ((unsigned)h < 64u && (unsigned)w < 64u)
                v = xb[((size_t)(ic0 + kk)) * HWPIX + h * 64 + w];
            ra[i] = v;
            rb[i] = wt[(size_t)(ic0 + kk) * OC + nb * 128 + (e & 127)];
        }
    };
    auto store_buf = [&](int buf) {
        #pragma unroll
        for (int i = 0; i < 8; ++i) {
            int e = i * 256 + tid;
            int kk = e >> 7, p = e & 127;
            As[buf][kk][p] = ra[i];
            Bs[buf][kk][p] = rb[i];
        }
    };

    prefetch(0);
    store_buf(0);
    __syncthreads();

    for (int g = 0; g < NCHUNK; ++g) {
        const int c = g & 31;
        const int cur = g & 1;

        if (c == 0) {
            #pragma unroll
            for (int r = 0; r < 8; ++r)
                #pragma unroll
                for (int cc = 0; cc < 8; ++cc) pt[r][cc] = 0.f;
        }

        const bool hasNext = (g + 1 < NCHUNK);
        if (hasNext) prefetch(g + 1);

        #pragma unroll
        for (int kk = 0; kk < BKK; ++kk) {
            float a[8], bb[8];
            #pragma unroll
            for (int r = 0; r < 8; ++r) a[r] = As[cur][kk][ty * 8 + r];
            #pragma unroll
            for (int cc = 0; cc < 8; ++cc) bb[cc] = Bs[cur][kk][tx * 8 + cc];
            #pragma unroll
            for (int r = 0; r < 8; ++r)
                #pragma unroll
                for (int cc = 0; cc < 8; ++cc)
                    pt[r][cc] = fmaf(a[r], bb[cc], pt[r][cc]);
        }

        if (hasNext) store_buf(cur ^ 1);
        __syncthreads();

        if (c == 31) {
            #pragma unroll
            for (int r = 0; r < 8; ++r)
                #pragma unroll
                for (int cc = 0; cc < 8; ++cc)
                    tot[r][cc] = __fadd_rn(tot[r][cc], pt[r][cc]);
        }
    }

    // epilogue: bias + relu -> NHWC
    #pragma unroll
    for (int r = 0; r < 8; ++r) {
        int p = ty * 8 + r;
        size_t rowbase = ((size_t)b * HWPIX + h0 * 64 + p) * OC + nb * 128 + tx * 8;
        #pragma unroll
        for (int c = 0; c < 8; ++c) {
            float v = __fadd_rn(tot[r][c], bsh[nb * 128 + tx * 8 + c]);
            g_shared[rowbase + c] = fmaxf(v, 0.f);
        }
    }
}

// ---------------------------------------------------------------------------
// k2: 1x1 heads + softmax + decode. 64-ic chunks, float4 staging loads
//     (high MLP on the 134MB g_shared read). Accumulator chain remains
//     strictly ic-ascending per output -> bit-identical to passing kernel.
// ---------------------------------------------------------------------------
#define XS_PITCH 68
__global__ __launch_bounds__(256) void k_heads(const float* __restrict__ bcls,
                                               const float* __restrict__ breg,
                                               float* __restrict__ out) {
    extern __shared__ float hsm[];
    float*  xs  = hsm;                            // [256][68]
    float4* ws4 = reinterpret_cast<float4*>(hsm + 256 * XS_PITCH);  // [64][14]

    const int tid = threadIdx.x;
    const int pixBase = blockIdx.x * 256;
    const int pix = pixBase + tid;

    float acc[56];
    #pragma unroll
    for (int o = 0; o < 56; ++o) acc[o] = 0.f;

    for (int ic0 = 0; ic0 < CIN; ic0 += 64) {
        // xs: 256 px x 64 ic as 4096 float4, 16 per thread
        #pragma unroll
        for (int i = 0; i < 16; ++i) {
            int e = i * 256 + tid;
            int px = e >> 4, q = e & 15;
            float4 v = *reinterpret_cast<const float4*>(
                &g_shared[(size_t)(pixBase + px) * OC + ic0 + q * 4]);
            float* d = &xs[px * XS_PITCH + q * 4];
            d[0] = v.x; d[1] = v.y; d[2] = v.z; d[3] = v.w;
        }
        // weights: 64 ic x 56 padded outputs
        for (int j = tid; j < 64 * 56; j += 256) {
            int ic = j / 56, o = j - ic * 56;
            reinterpret_cast<float*>(&ws4[ic * 14])[o] =
                (o < 54) ? g_wk[(ic0 + ic) * 54 + o] : 0.f;
        }
        __syncthreads();
        #pragma unroll 4
        for (int ic = 0; ic < 64; ++ic) {
            float v = xs[tid * XS_PITCH + ic];
            #pragma unroll
            for (int o4 = 0; o4 < 14; ++o4) {
                float4 w = ws4[ic * 14 + o4];
                acc[o4 * 4 + 0] = fmaf(v, w.x, acc[o4 * 4 + 0]);
                acc[o4 * 4 + 1] = fmaf(v, w.y, acc[o4 * 4 + 1]);
                acc[o4 * 4 + 2] = fmaf(v, w.z, acc[o4 * 4 + 2]);
                acc[o4 * 4 + 3] = fmaf(v, w.w, acc[o4 * 4 + 3]);
            }
        }
        __syncthreads();
    }

    const int b  = pix >> 12;
    const int pi = pix & 4095;
    const int h  = pi >> 6, w = pi & 63;

    #pragma unroll
    for (int o = 0; o < 18; ++o) acc[o] = __fadd_rn(acc[o], bcls[o]);
    #pragma unroll
    for (int o = 18; o < 54; ++o) acc[o] = __fadd_rn(acc[o], breg[o - 18]);

    const float shx = (float)(w * 16);
    const float shy = (float)(h * 16);

    #pragma unroll
    for (int a = 0; a < NA; ++a) {
        float l0 = acc[2 * a], l1 = acc[2 * a + 1];
        float m = fmaxf(l0, l1);
        float e0 = expf(__fsub_rn(l0, m)), e1 = expf(__fsub_rn(l1, m));
        float s = __fadd_rn(e0, e1);
        float p0 = __fdiv_rn(e0, s), p1 = __fdiv_rn(e1, s);

        size_t n = (size_t)b * NANCH + (size_t)pi * NA + a;
        out[CLS_OFF + n * 2]     = p0;
        out[CLS_OFF + n * 2 + 1] = p1;

        float dxv = acc[18 + a * 4 + 0];
        float dyv = acc[18 + a * 4 + 1];
        float dwv = acc[18 + a * 4 + 2];
        float dhv = acc[18 + a * 4 + 3];
        out[n * 4 + 0] = dxv;
        out[n * 4 + 1] = dyv;
        out[n * 4 + 2] = dwv;
        out[n * 4 + 3] = dhv;

        float ax1 = __fadd_rn(shx, g_abase[a * 4 + 0]);
        float ay1 = __fadd_rn(shy, g_abase[a * 4 + 1]);
        float ax2 = __fadd_rn(shx, g_abase[a * 4 + 2]);
        float ay2 = __fadd_rn(shy, g_abase[a * 4 + 3]);
        float aw = __fsub_rn(ax2, ax1);
        float ah = __fsub_rn(ay2, ay1);
        float actx = __fadd_rn(ax1, __fmul_rn(0.5f, aw));
        float acty = __fadd_rn(ay1, __fmul_rn(0.5f, ah));
        float cx = __fadd_rn(__fmul_rn(dxv, aw), actx);
        float cy = __fadd_rn(__fmul_rn(dyv, ah), acty);
        float bw = __fmul_rn(expf(dwv), aw);
        float bh = __fmul_rn(expf(dhv), ah);
        float x1 = __fsub_rn(cx, __fmul_rn(0.5f, bw));
        float y1 = __fsub_rn(cy, __fmul_rn(0.5f, bh));
        float x2 = __fadd_rn(cx, __fmul_rn(0.5f, bw));
        float y2 = __fadd_rn(cy, __fmul_rn(0.5f, bh));
        x1 = fminf(fmaxf(x1, 0.f), 1024.f);
        y1 = fminf(fmaxf(y1, 0.f), 1024.f);
        x2 = fminf(fmaxf(x2, 0.f), 1024.f);
        y2 = fminf(fmaxf(y2, 0.f), 1024.f);
        float wsz = __fsub_rn(x2, x1), hsz = __fsub_rn(y2, y1);
        float sc = (wsz >= 16.f && hsz >= 16.f) ? p1 : NEGF;

        g_boxes[n * 4 + 0] = x1;
        g_boxes[n * 4 + 1] = y1;
        g_boxes[n * 4 + 2] = x2;
        g_boxes[n * 4 + 3] = y2;
        g_scores[n] = sc;
    }
}

// ---------------------------------------------------------------------------
// k3: per-image exact top-6000 set, stable (index-ordered) compaction
// ---------------------------------------------------------------------------
__device__ __forceinline__ unsigned score_key(float f) {
    unsigned u = __float_as_uint(f);
    return (u & 0x80000000u) ? ~u : (u | 0x80000000u);
}

__global__ __launch_bounds__(1024) void k_select() {
    const int b = blockIdx.x;
    const int tid = threadIdx.x;
    const int warp = tid >> 5, lane = tid & 31;
    const float* sc = g_scores + (size_t)b * NANCH;
    __shared__ unsigned hist[256];
    __shared__ unsigned sel_prefix;
    __shared__ int sel_needed;
    __shared__ int warpG[32], warpE[32];
    __shared__ int base_g, base_e;

    unsigned prefix = 0, maskHi = 0;
    int needed = PRE_NMS;

    for (int shift = 24; shift >= 0; shift -= 8) {
        for (int i = tid; i < 256; i += 1024) hist[i] = 0;
        __syncthreads();
        for (int j = tid; j < NANCH; j += 1024) {
            unsigned u = score_key(sc[j]);
            if ((u & maskHi) == prefix)
                atomicAdd(&hist[(u >> shift) & 255u], 1u);
        }
        __syncthreads();
        if (tid == 0) {
            int need = needed;
            int bsel = 0;
            for (int bin = 255; bin >= 0; --bin) {
                int c = (int)hist[bin];
                if (c >= need) { bsel = bin; break; }
                need -= c;
            }
            sel_needed = need;
            sel_prefix = prefix | ((unsigned)bsel << shift);
        }
        __syncthreads();
        needed = sel_needed;
        prefix = sel_prefix;
        maskHi |= (0xFFu << shift);
        __syncthreads();
    }

    const unsigned T = prefix;
    const int needEq = needed;
    const int cgt = PRE_NMS - needEq;

    if (tid == 0) { base_g = 0; base_e = 0; }
    __syncthreads();

    const unsigned lt_mask = (1u << lane) - 1u;
    const float4* bp = reinterpret_cast<const float4*>(g_boxes);

    for (int chunk = 0; chunk < NANCH; chunk += 1024) {
        int j = chunk + tid;
        float s = sc[j];
        unsigned u = score_key(s);
        bool isG = (u > T);
        bool isE = (u == T);
        unsigned gm = __ballot_sync(0xffffffffu, isG);
        unsigned em = __ballot_sync(0xffffffffu, isE);
        if (lane == 0) { warpG[warp] = __popc(gm); warpE[warp] = __popc(em); }
        __syncthreads();
        if (warp == 0) {
            int g = warpG[lane], e = warpE[lane];
            #pragma unroll
            for (int off = 1; off < 32; off <<= 1) {
                int go = __shfl_up_sync(0xffffffffu, g, off);
                int eo = __shfl_up_sync(0xffffffffu, e, off);
                if (lane >= off) { g += go; e += eo; }
            }
            warpG[lane] = g; warpE[lane] = e;
        }
        __syncthreads();
        int wbaseG = (warp == 0) ? 0 : warpG[warp - 1];
        int wbaseE = (warp == 0) ? 0 : warpE[warp - 1];
        int slot = -1;
        if (isG) {
            slot = base_g + wbaseG + __popc(gm & lt_mask);
        } else if (isE) {
            int er = base_e + wbaseE + __popc(em & lt_mask);
            if (er < needEq) slot = cgt + er;
        }
        if (slot >= 0) {
            size_t n = (size_t)b * NANCH + j;
            g_cand_s[b * PRE_NMS + slot] = s;
            g_cand_b[b * PRE_NMS + slot] = bp[n];
        }
        __syncthreads();
        if (tid == 0) { base_g += warpG[31]; base_e += warpE[31]; }
        __syncthreads();
    }
}

// ---------------------------------------------------------------------------
// k4: sort-then-sweep greedy NMS (passing semantics; unchanged)
// ---------------------------------------------------------------------------
#define NMS_THREADS 512
#define NMS_N 8192
__global__ __launch_bounds__(NMS_THREADS) void k_nms(float* __restrict__ out) {
    extern __shared__ unsigned char smem_raw[];
    float4* bx = reinterpret_cast<float4*>(smem_raw);                     // [6000]
    unsigned long long* keys =
        reinterpret_cast<unsigned long long*>(smem_raw + PRE_NMS * 16);   // [8192]
    float* sc = reinterpret_cast<float*>(smem_raw + PRE_NMS * 16 + NMS_N * 8); // [6000]
    unsigned char* sup = smem_raw + PRE_NMS * 16 + NMS_N * 8 + PRE_NMS * 4;    // [8192]
    int* ctrl = reinterpret_cast<int*>(sup + NMS_N);                      // [4]

    const int b = blockIdx.x;
    const int tid = threadIdx.x;

    for (int j = tid; j < NMS_N; j += NMS_THREADS) {
        if (j < PRE_NMS) {
            float s = g_cand_s[b * PRE_NMS + j];
            sc[j] = s;
            bx[j] = g_cand_b[b * PRE_NMS + j];
            unsigned long long key =
                ((unsigned long long)score_key(s) << 32) | (unsigned)(~j);
            keys[j] = ~key;
        } else {
            keys[j] = ~0ull;
        }
        sup[j] = 0;
    }
    if (tid == 0) ctrl[0] = 0;
    __syncthreads();

    for (int k = 2; k <= NMS_N; k <<= 1) {
        for (int j = k >> 1; j > 0; j >>= 1) {
            for (int t = tid; t < NMS_N; t += NMS_THREADS) {
                int partner = t ^ j;
                if (partner > t) {
                    bool up = ((t & k) == 0);
                    unsigned long long a = keys[t], c = keys[partner];
                    if (up ? (a > c) : (a < c)) {
                        keys[t] = c; keys[partner] = a;
                    }
                }
            }
            __syncthreads();
        }
    }

    for (int it = 0; it < POST_NMS; ++it) {
        if (tid == 0) {
            int p = ctrl[0];
            while (p < PRE_NMS && sup[p]) ++p;
            ctrl[0] = p;
        }
        __syncthreads();
        int pos = ctrl[0];

        bool valid = false;
        int slot = 0;
        float m = 0.f;
        if (pos < PRE_NMS) {
            slot = (int)(unsigned)keys[pos];
            m = sc[slot];
            valid = (m > NEGF);
        }

        if (!valid) {
            int remain = (POST_NMS - it) * 5;
            float* ro = out + ROIS_OFF + ((size_t)b * POST_NMS + it) * 5;
            for (int k2 = tid; k2 < remain; k2 += NMS_THREADS) ro[k2] = 0.f;
            return;
        }

        float4 B = bx[slot];
        if (tid == 0) {
            float* ro = out + ROIS_OFF + ((size_t)b * POST_NMS + it) * 5;
            ro[0] = m; ro[1] = B.x; ro[2] = B.y; ro[3] = B.z; ro[4] = B.w;
            sup[pos] = 1;
        }
        float a1 = __fmul_rn(__fsub_rn(B.z, B.x), __fsub_rn(B.w, B.y));
        for (int p2 = pos + 1 + tid; p2 < PRE_NMS; p2 += NMS_THREADS) {
            if (sup[p2]) continue;
            int s2 = (int)(unsigned)keys[p2];
            float4 c = bx[s2];
            float x1 = fmaxf(B.x, c.x);
            float y1 = fmaxf(B.y, c.y);
            float x2 = fminf(B.z, c.z);
            float y2 = fminf(B.w, c.w);
            float inter = __fmul_rn(fmaxf(__fsub_rn(x2, x1), 0.f),
                                    fmaxf(__fsub_rn(y2, y1), 0.f));
            float a2 = __fmul_rn(__fsub_rn(c.z, c.x), __fsub_rn(c.w, c.y));
            float denom = __fadd_rn(__fsub_rn(__fadd_rn(a1, a2), inter), 1e-9f);
            float iou = __fdiv_rn(inter, denom);
            if (iou >= 0.7f) sup[p2] = 1;
        }
        __syncthreads();
    }
}

// ---------------------------------------------------------------------------
// launch
// ---------------------------------------------------------------------------
extern "C" void kernel_launch(void* const* d_in, const int* in_sizes, int n_in,
                              void* d_out, int out_size) {
    (void)in_sizes; (void)n_in; (void)out_size;
    const float* x     = (const float*)d_in[0];
    const float* Wsh   = (const float*)d_in[1];
    const float* bsh   = (const float*)d_in[2];
    const float* Wcls  = (const float*)d_in[3];
    const float* bcls  = (const float*)d_in[4];
    const float* Wreg  = (const float*)d_in[5];
    const float* breg  = (const float*)d_in[6];
    float* out = (float*)d_out;

    k_wt_transform<<<(OC*CIN*9 + 255) / 256, 256>>>(Wsh);
    k_wk_build<<<(CIN*54 + 255) / 256, 256>>>(Wcls, Wreg);

    dim3 cgrid(4, 512);
    k_conv3x3<<<cgrid, 256>>>(x, bsh);

    int heads_smem = 256 * XS_PITCH * 4 + 64 * 14 * 16;   // 83968 B
    cudaFuncSetAttribute(k_heads, cudaFuncAttributeMaxDynamicSharedMemorySize, heads_smem);
    k_heads<<<NPIX / 256, 256, heads_smem>>>(bcls, breg, out);

    k_select<<<BATCH, 1024>>>();

    int smem_bytes = PRE_NMS * 16 + NMS_N * 8 + PRE_NMS * 4 + NMS_N + 16;
    cudaFuncSetAttribute(k_nms, cudaFuncAttributeMaxDynamicSharedMemorySize, smem_bytes);
    k_nms<<<BATCH, NMS_THREADS, smem_bytes>>>(out);
}